// round 10
// baseline (speedup 1.0000x reference)
#include <cuda_runtime.h>
#include <math.h>

// Fused SSIM loss, (w,d)=(v1+v2,v1-v2) basis, separable 11x11 Gaussian.
// TY=40 tiles w/ 5-row v-pass blocking, symmetric-G register compression,
// conflict-free smem, single kernel with block-counter finalize.
// im1, im2: (32,3,512,512) fp32; window: (3,1,11,11) fp32 outer(g,g).

#define TX 32
#define TY 40
#define HALO 5
#define RX 42
#define RY 50          // TY + 10
#define IMG 512
#define NPLANES 96
#define NPIX 25165824.0
#define GRIDY 13       // ceil(512/40); last tile masks rows >= 512
#define NBLOCKS (16 * GRIDY * 96)   // 19968

// conflict-free strides
#define S12_STR 46     // u64 units;  92 words/row  (28 mod 32)
#define HB_STR  33     // float4 units; 132 words/row (4 mod 32)

// dynamic smem layout (bytes)
#define OFF_S12   0
#define SZ_S12    (RY * S12_STR * 8)            // 18400
#define OFF_HB    (OFF_S12 + SZ_S12)
#define SZ_HB     (RY * HB_STR * 16)            // 26400
#define OFF_GGP   (OFF_HB + SZ_HB)
#define OFF_WS    (OFF_GGP + 11 * 8)
#define SMEM_TOT  (OFF_WS + 8 * 4)              // ~43.9 KB -> 5 blocks/SM

// symmetric Gaussian: g[k] == g[10-k], keep 6 unique registers
#define GS(k) G[((k) <= 5) ? (k) : (10 - (k))]

typedef unsigned long long u64;

__device__ __forceinline__ u64 pk2(float a, float b) {
    u64 r; asm("mov.b64 %0,{%1,%2};" : "=l"(r) : "f"(a), "f"(b)); return r;
}
__device__ __forceinline__ void unpk(u64 v, float& a, float& b) {
    asm("mov.b64 {%0,%1},%2;" : "=f"(a), "=f"(b) : "l"(v));
}
__device__ __forceinline__ u64 fma2(u64 a, u64 b, u64 c) {
    u64 d; asm("fma.rn.f32x2 %0,%1,%2,%3;" : "=l"(d) : "l"(a), "l"(b), "l"(c)); return d;
}
__device__ __forceinline__ u64 mul2(u64 a, u64 b) {
    u64 d; asm("mul.rn.f32x2 %0,%1,%2;" : "=l"(d) : "l"(a), "l"(b)); return d;
}

__device__ double g_accum = 0.0;
__device__ unsigned int g_ctr = 0;

__global__ void __launch_bounds__(256, 5)
ssim_main_kernel(const float* __restrict__ im1,
                 const float* __restrict__ im2,
                 const float* __restrict__ window,
                 float* __restrict__ out)
{
    extern __shared__ char sm_raw[];
    u64*    swd    = (u64*)   (sm_raw + OFF_S12);   // packed (w,d) input tile
    float4* hb     = (float4*)(sm_raw + OFF_HB);    // (Mw,Md,Sw,Sd) h-moments
    u64*    ggp    = (u64*)   (sm_raw + OFF_GGP);
    float*  warpsum= (float*) (sm_raw + OFF_WS);

    const int tid = threadIdx.x;

    // 1-D Gaussian from outer-product window: g[k] = w[5][k]/sqrt(w[5][5])
    if (tid < 11) {
        float g5 = sqrtf(window[5 * 11 + 5]);
        float g  = window[5 * 11 + tid] / g5;
        ggp[tid] = pk2(g, g);
    }

    const int x0 = blockIdx.x * TX;
    const int y0 = blockIdx.y * TY;
    const long plane = (long)blockIdx.z * (IMG * IMG);
    const float* __restrict__ p1 = im1 + plane;
    const float* __restrict__ p2 = im2 + plane;

    // ---- load 50x42 tile as packed (w,d), zero padded ----
    #pragma unroll
    for (int i = 0; i < 9; i++) {
        int idx = tid + i * 256;
        if (idx < RY * RX) {
            int r = idx / RX;
            int c = idx - r * RX;
            int gy = y0 + r - HALO;
            int gx = x0 + c - HALO;
            float v1 = 0.0f, v2 = 0.0f;
            if ((unsigned)gy < (unsigned)IMG && (unsigned)gx < (unsigned)IMG) {
                int o = gy * IMG + gx;
                v1 = p1[o];
                v2 = p2[o];
            }
            swd[r * S12_STR + c] = pk2(v1 + v2, v1 - v2);
        }
    }
    __syncthreads();

    u64 G[6];    // symmetric: k and 10-k share
    #pragma unroll
    for (int k = 0; k < 6; k++) G[k] = ggp[k];

    // ---- horizontal pass: 50 rows x 8 groups of 4 cols = 400 items ----
    for (int it = tid; it < RY * 8; it += 256) {
        int r  = it % RY;
        int c0 = (it / RY) * 4;

        u64 aM[4] = {0, 0, 0, 0};     // conv of (w,d)
        u64 aS[4] = {0, 0, 0, 0};     // conv of (w^2,d^2)

        const ulonglong2* ps = (const ulonglong2*)(swd + r * S12_STR + c0);
        #pragma unroll
        for (int ii = 0; ii < 7; ii++) {
            ulonglong2 q = ps[ii];
            #pragma unroll
            for (int h = 0; h < 2; h++) {
                const int i = 2 * ii + h;
                u64 v = h ? q.y : q.x;
                u64 s = mul2(v, v);
                #pragma unroll
                for (int j = 0; j < 4; j++) {
                    const int k = i - j;
                    if (k >= 0 && k <= 10) {
                        aM[j] = fma2(GS(k), v, aM[j]);
                        aS[j] = fma2(GS(k), s, aS[j]);
                    }
                }
            }
        }

        #pragma unroll
        for (int j = 0; j < 4; j++) {
            float mw, md, sw, sd;
            unpk(aM[j], mw, md);
            unpk(aS[j], sw, sd);
            hb[r * HB_STR + c0 + j] = make_float4(mw, md, sw, sd);
        }
    }
    __syncthreads();

    // ---- vertical pass: each thread computes 5 rows of one column ----
    const int x  = tid & 31;
    const int yb = (tid >> 5) * 5;

    u64 accM[5] = {0, 0, 0, 0, 0};
    u64 accS[5] = {0, 0, 0, 0, 0};

    #pragma unroll
    for (int i = 0; i < 15; i++) {
        float4 q = hb[(yb + i) * HB_STR + x];
        u64 m = pk2(q.x, q.y);
        u64 s = pk2(q.z, q.w);
        #pragma unroll
        for (int j = 0; j < 5; j++) {
            const int k = i - j;
            if (k >= 0 && k <= 10) {
                accM[j] = fma2(GS(k), m, accM[j]);
                accS[j] = fma2(GS(k), s, accS[j]);
            }
        }
    }

    // ---- SSIM epilogue in (w,d) basis, mask rows beyond image ----
    const float C1 = 1e-4f;
    const float C2 = 9e-4f;
    float lsum = 0.0f;
    #pragma unroll
    for (int j = 0; j < 5; j++) {
        float mw, md, sw, sd;
        unpk(accM[j], mw, md);
        unpk(accS[j], sw, sd);
        float P = mw * mw;
        float Q = md * md;
        float pd = 0.5f * (P - Q);            // 2*mu1*mu2
        float ps = 0.5f * (P + Q);            // mu1^2 + mu2^2
        float num = (pd + C1) * (0.5f * (sw - sd) - pd + C2);
        float den = (ps + C1) * (0.5f * (sw + sd) - ps + C2);
        float v = __fdividef(num, den);
        if (y0 + yb + j < IMG) lsum += v;
    }

    // ---- block reduction + global accumulate + finalize ----
    #pragma unroll
    for (int o = 16; o > 0; o >>= 1)
        lsum += __shfl_down_sync(0xffffffffu, lsum, o);
    if ((tid & 31) == 0) warpsum[tid >> 5] = lsum;
    __syncthreads();
    if (tid == 0) {
        float t = 0.f;
        #pragma unroll
        for (int i = 0; i < 8; i++) t += warpsum[i];
        atomicAdd(&g_accum, (double)t);
        __threadfence();
        unsigned old = atomicAdd(&g_ctr, 1u);
        if (old == NBLOCKS - 1) {
            __threadfence();
            double a = *(volatile double*)&g_accum;
            out[0] = (float)(-a / NPIX);
            *(volatile double*)&g_accum = 0.0;
            *(volatile unsigned int*)&g_ctr = 0u;
            __threadfence();
        }
    }
}

extern "C" void kernel_launch(void* const* d_in, const int* in_sizes, int n_in,
                              void* d_out, int out_size)
{
    const float* im1 = (const float*)d_in[0];
    const float* im2 = (const float*)d_in[1];
    const float* win = (const float*)d_in[2];
    float* out = (float*)d_out;

    cudaFuncSetAttribute(ssim_main_kernel,
                         cudaFuncAttributeMaxDynamicSharedMemorySize, SMEM_TOT);
    dim3 grid(IMG / TX, GRIDY, NPLANES);
    ssim_main_kernel<<<grid, 256, SMEM_TOT>>>(im1, im2, win, out);
}

// round 13
// speedup vs baseline: 1.0283x; 1.0283x over previous
#include <cuda_runtime.h>
#include <math.h>

// Fused SSIM loss, (w,d)=(v1+v2,v1-v2) basis, separable 11x11 Gaussian.
// TY=32 tile (R9 base), symmetric-G register compression, 6 blocks/SM target.
// im1, im2: (32,3,512,512) fp32; window: (3,1,11,11) fp32 outer(g,g).
// (Second resubmission: Rounds 11 and 12 both hit broker/container infra
//  failures before the harness ran; kernel analysis shows no crash path.)

#define TX 32
#define TY 32
#define HALO 5
#define RX 42
#define RY 42
#define IMG 512
#define NPLANES 96
#define NPIX 25165824.0
#define NBLOCKS (16 * 16 * 96)   // 24576

// conflict-free strides
#define S12_STR 46     // u64 units;  92 words/row  (28 mod 32)
#define HB_STR  33     // float4 units; 132 words/row (4 mod 32)

// dynamic smem layout (bytes)
#define OFF_S12   0
#define SZ_S12    (RY * S12_STR * 8)            // 15456
#define OFF_HB    (OFF_S12 + SZ_S12)
#define SZ_HB     (RY * HB_STR * 16)            // 22176
#define OFF_GGP   (OFF_HB + SZ_HB)
#define OFF_WS    (OFF_GGP + 11 * 8)
#define SMEM_TOT  (OFF_WS + 8 * 4)              // 37752 B -> 6 blocks/SM

// symmetric Gaussian: g[k] == g[10-k], keep 6 unique packed registers
#define GS(k) G[((k) <= 5) ? (k) : (10 - (k))]

typedef unsigned long long u64;

__device__ __forceinline__ u64 pk2(float a, float b) {
    u64 r; asm("mov.b64 %0,{%1,%2};" : "=l"(r) : "f"(a), "f"(b)); return r;
}
__device__ __forceinline__ void unpk(u64 v, float& a, float& b) {
    asm("mov.b64 {%0,%1},%2;" : "=f"(a), "=f"(b) : "l"(v));
}
__device__ __forceinline__ u64 fma2(u64 a, u64 b, u64 c) {
    u64 d; asm("fma.rn.f32x2 %0,%1,%2,%3;" : "=l"(d) : "l"(a), "l"(b), "l"(c)); return d;
}
__device__ __forceinline__ u64 mul2(u64 a, u64 b) {
    u64 d; asm("mul.rn.f32x2 %0,%1,%2;" : "=l"(d) : "l"(a), "l"(b)); return d;
}

__device__ double g_accum = 0.0;
__device__ unsigned int g_ctr = 0;

__global__ void __launch_bounds__(256, 6)
ssim_main_kernel(const float* __restrict__ im1,
                 const float* __restrict__ im2,
                 const float* __restrict__ window,
                 float* __restrict__ out)
{
    extern __shared__ char sm_raw[];
    u64*    swd    = (u64*)   (sm_raw + OFF_S12);   // packed (w,d) input tile
    float4* hb     = (float4*)(sm_raw + OFF_HB);    // (Mw,Md,Sw,Sd) h-moments
    u64*    ggp    = (u64*)   (sm_raw + OFF_GGP);
    float*  warpsum= (float*) (sm_raw + OFF_WS);

    const int tid = threadIdx.x;

    // 1-D Gaussian from outer-product window: g[k] = w[5][k]/sqrt(w[5][5])
    if (tid < 11) {
        float g5 = sqrtf(window[5 * 11 + 5]);
        float g  = window[5 * 11 + tid] / g5;
        ggp[tid] = pk2(g, g);
    }

    const int x0 = blockIdx.x * TX;
    const int y0 = blockIdx.y * TY;
    const long plane = (long)blockIdx.z * (IMG * IMG);
    const float* __restrict__ p1 = im1 + plane;
    const float* __restrict__ p2 = im2 + plane;

    // ---- load 42x42 tile as packed (w,d), zero padded ----
    #pragma unroll
    for (int i = 0; i < 7; i++) {
        int idx = tid + i * 256;
        if (idx < RY * RX) {
            int r = idx / RX;
            int c = idx - r * RX;
            int gy = y0 + r - HALO;
            int gx = x0 + c - HALO;
            float v1 = 0.0f, v2 = 0.0f;
            if ((unsigned)gy < (unsigned)IMG && (unsigned)gx < (unsigned)IMG) {
                int o = gy * IMG + gx;
                v1 = p1[o];
                v2 = p2[o];
            }
            swd[r * S12_STR + c] = pk2(v1 + v2, v1 - v2);
        }
    }
    __syncthreads();

    u64 G[6];    // symmetric: tap k shares with 10-k
    #pragma unroll
    for (int k = 0; k < 6; k++) G[k] = ggp[k];

    // ---- horizontal pass: consecutive tid -> consecutive r (conflict-free) ----
    for (int it = tid; it < RY * 8; it += 256) {
        int r  = it % RY;
        int c0 = (it / RY) * 4;

        u64 aM[4] = {0, 0, 0, 0};     // conv of (w,d)
        u64 aS[4] = {0, 0, 0, 0};     // conv of (w^2,d^2)

        const ulonglong2* ps = (const ulonglong2*)(swd + r * S12_STR + c0);
        #pragma unroll
        for (int ii = 0; ii < 7; ii++) {
            ulonglong2 q = ps[ii];
            #pragma unroll
            for (int h = 0; h < 2; h++) {
                const int i = 2 * ii + h;
                u64 v = h ? q.y : q.x;
                u64 s = mul2(v, v);
                #pragma unroll
                for (int j = 0; j < 4; j++) {
                    const int k = i - j;
                    if (k >= 0 && k <= 10) {
                        aM[j] = fma2(GS(k), v, aM[j]);
                        aS[j] = fma2(GS(k), s, aS[j]);
                    }
                }
            }
        }

        #pragma unroll
        for (int j = 0; j < 4; j++) {
            float mw, md, sw, sd;
            unpk(aM[j], mw, md);
            unpk(aS[j], sw, sd);
            hb[r * HB_STR + c0 + j] = make_float4(mw, md, sw, sd);
        }
    }
    __syncthreads();

    // ---- vertical pass: each thread computes 4 rows of one column ----
    const int x  = tid & 31;
    const int yb = (tid >> 5) * 4;

    u64 accM[4] = {0, 0, 0, 0};
    u64 accS[4] = {0, 0, 0, 0};

    #pragma unroll
    for (int i = 0; i < 14; i++) {
        float4 q = hb[(yb + i) * HB_STR + x];
        u64 m = pk2(q.x, q.y);
        u64 s = pk2(q.z, q.w);
        #pragma unroll
        for (int j = 0; j < 4; j++) {
            const int k = i - j;
            if (k >= 0 && k <= 10) {
                accM[j] = fma2(GS(k), m, accM[j]);
                accS[j] = fma2(GS(k), s, accS[j]);
            }
        }
    }

    // ---- SSIM epilogue in (w,d) basis ----
    const float C1 = 1e-4f;
    const float C2 = 9e-4f;
    float lsum = 0.0f;
    #pragma unroll
    for (int j = 0; j < 4; j++) {
        float mw, md, sw, sd;
        unpk(accM[j], mw, md);
        unpk(accS[j], sw, sd);
        float P = mw * mw;
        float Q = md * md;
        float pd = 0.5f * (P - Q);            // 2*mu1*mu2
        float ps = 0.5f * (P + Q);            // mu1^2 + mu2^2
        float num = (pd + C1) * (0.5f * (sw - sd) - pd + C2);
        float den = (ps + C1) * (0.5f * (sw + sd) - ps + C2);
        lsum += __fdividef(num, den);
    }

    // ---- block reduction + global accumulate + finalize ----
    #pragma unroll
    for (int o = 16; o > 0; o >>= 1)
        lsum += __shfl_down_sync(0xffffffffu, lsum, o);
    if ((tid & 31) == 0) warpsum[tid >> 5] = lsum;
    __syncthreads();
    if (tid == 0) {
        float t = 0.f;
        #pragma unroll
        for (int i = 0; i < 8; i++) t += warpsum[i];
        atomicAdd(&g_accum, (double)t);
        __threadfence();
        unsigned old = atomicAdd(&g_ctr, 1u);
        if (old == NBLOCKS - 1) {
            __threadfence();
            double a = *(volatile double*)&g_accum;
            out[0] = (float)(-a / NPIX);
            *(volatile double*)&g_accum = 0.0;
            *(volatile unsigned int*)&g_ctr = 0u;
            __threadfence();
        }
    }
}

extern "C" void kernel_launch(void* const* d_in, const int* in_sizes, int n_in,
                              void* d_out, int out_size)
{
    const float* im1 = (const float*)d_in[0];
    const float* im2 = (const float*)d_in[1];
    const float* win = (const float*)d_in[2];
    float* out = (float*)d_out;

    cudaFuncSetAttribute(ssim_main_kernel,
                         cudaFuncAttributeMaxDynamicSharedMemorySize, SMEM_TOT);
    dim3 grid(IMG / TX, IMG / TY, NPLANES);
    ssim_main_kernel<<<grid, 256, SMEM_TOT>>>(im1, im2, win, out);
}